// round 11
// baseline (speedup 1.0000x reference)
#include <cuda_runtime.h>
#include <cuda_fp16.h>

#define NMAX 100000
#define EMAX 1600000
#define CMAX 128

// Scratch (__device__ globals: allocation-free rule)
__device__ __half d_G[(size_t)NMAX * CMAX];       // messages (half)
__device__ __half d_B1[(size_t)NMAX * CMAX];      // activations (half)
__device__ __half d_B2[(size_t)NMAX * CMAX];
__device__ float  d_dinv[NMAX];
__device__ int    d_cnt[NMAX];
__device__ int    d_cur[NMAX];
__device__ int    d_off[NMAX + 1];
__device__ int    d_csr[EMAX];
__device__ int    d_blk[128];
__device__ int    d_blk2[128];
__device__ unsigned d_gmin[64];

__device__ __forceinline__ unsigned enc_f(float f) {
    unsigned u = __float_as_uint(f);
    return (u & 0x80000000u) ? ~u : (u | 0x80000000u);
}
__device__ __forceinline__ float dec_f(unsigned e) {
    unsigned u = (e & 0x80000000u) ? (e ^ 0x80000000u) : ~e;
    return __uint_as_float(u);
}

// 4 halves (8B) from fp32 or half source row
__device__ __forceinline__ uint2 loadH4(const float* A, size_t row, int k4) {
    float4 v = __ldg((const float4*)(A + row * 128) + k4);
    __half2 h0 = __floats2half2_rn(v.x, v.y);
    __half2 h1 = __floats2half2_rn(v.z, v.w);
    uint2 r;
    r.x = *(unsigned*)&h0;
    r.y = *(unsigned*)&h1;
    return r;
}
__device__ __forceinline__ uint2 loadH4(const __half* A, size_t row, int k4) {
    return __ldg((const uint2*)(A + row * 128) + k4);
}

// ================= degree histogram =================
__global__ void k_hist(const int* __restrict__ dst, int E) {
    int i = blockIdx.x * blockDim.x + threadIdx.x;
    if (i < E) atomicAdd(&d_cnt[dst[i]], 1);
}

// ================= CSR scans =================
__global__ void k_scan1(int N) {
    __shared__ int sh[256];
    int t = threadIdx.x;
    int base = blockIdx.x * 1024 + t * 4;
    int c0 = 0, c1 = 0, c2 = 0, c3 = 0;
    if (base + 3 < N) {
        int4 v = *(const int4*)&d_cnt[base];
        c0 = v.x; c1 = v.y; c2 = v.z; c3 = v.w;
    } else {
        if (base + 0 < N) c0 = d_cnt[base + 0];
        if (base + 1 < N) c1 = d_cnt[base + 1];
        if (base + 2 < N) c2 = d_cnt[base + 2];
        if (base + 3 < N) c3 = d_cnt[base + 3];
    }
    int s = c0 + c1 + c2 + c3;
    sh[t] = s;
    __syncthreads();
    for (int d = 1; d < 256; d <<= 1) {
        int v = (t >= d) ? sh[t - d] : 0;
        __syncthreads();
        sh[t] += v;
        __syncthreads();
    }
    int excl = sh[t] - s;
    if (base + 0 < N) d_off[base + 0] = excl;
    if (base + 1 < N) d_off[base + 1] = excl + c0;
    if (base + 2 < N) d_off[base + 2] = excl + c0 + c1;
    if (base + 3 < N) d_off[base + 3] = excl + c0 + c1 + c2;
    if (t == 255) d_blk[blockIdx.x] = sh[255];
}

__global__ void k_scan2(int nblk) {
    __shared__ int sh[128];
    int t = threadIdx.x;
    int v = (t < nblk) ? d_blk[t] : 0;
    sh[t] = v;
    __syncthreads();
    for (int d = 1; d < 128; d <<= 1) {
        int u = (t >= d) ? sh[t - d] : 0;
        __syncthreads();
        sh[t] += u;
        __syncthreads();
    }
    d_blk2[t] = sh[t] - v;
}

// Also: computes dinv, zeroes d_cnt/d_cur for graph replay, inits gmin.
__global__ void k_scan3(int N, int E) {
    int i = blockIdx.x * blockDim.x + threadIdx.x;
    if (i < N) {
        d_off[i] += d_blk2[i >> 10];
        d_dinv[i] = rsqrtf((float)d_cnt[i] + 1.0f);  // +1 self-loop
        d_cnt[i] = 0;                                 // self-clean for replay
        d_cur[i] = 0;
    }
    if (i == 0) d_off[N] = E;
    if (blockIdx.x == 0 && threadIdx.x < 64) d_gmin[threadIdx.x] = 0xFFFFFFFFu;
}

// ================= tensor-core GEMM =================
// g[row] = half(dinv[row] * (A[row] @ W)); A: [N][128] (fp32 or half), W: [128][COLS] fp32.
// 256 threads; tile = 128 rows x COLS. Warp w computes rows w*16..w*16+15 via
// mma.sync.m16n8k16 (f16 in, f32 accum). Smem rows padded (272B / 144B).
// FILL: blocks with bid < fillBlocks do the CSR fill instead.
template <int COLS, bool FILL, typename AT>
__global__ void __launch_bounds__(256)
k_gemm_mma(const AT* __restrict__ A, const float* __restrict__ W,
           __half* __restrict__ g, int N,
           const int* __restrict__ src, const int* __restrict__ dstp, int E, int fillBlocks)
{
    if (FILL && (int)blockIdx.x < fillBlocks) {
        for (int i = blockIdx.x * 256 + threadIdx.x; i < E; i += fillBlocks * 256) {
            int d = dstp[i];
            int p = atomicAdd(&d_cur[d], 1);
            d_csr[d_off[d] + p] = src[i];
        }
        return;
    }
    constexpr int AROW = 272;
    constexpr int WROW = (COLS == 128) ? 272 : 144;
    constexpr int NT = COLS / 8;

    extern __shared__ char sm[];
    char* smA = sm;
    char* smW = sm + 128 * AROW;
    const unsigned sA = (unsigned)__cvta_generic_to_shared(smA);
    const unsigned sW = (unsigned)__cvta_generic_to_shared(smW);

    const int tid = threadIdx.x;
    const int base = (blockIdx.x - (FILL ? fillBlocks : 0)) * 128;

    for (int i = tid; i < 128 * 32; i += 256) {
        int r = i >> 5, k4 = i & 31;
        int row = base + r;
        uint2 v = make_uint2(0u, 0u);
        if (row < N) v = loadH4(A, (size_t)row, k4);
        *(uint2*)(smA + r * AROW + k4 * 8) = v;
    }
    for (int i = tid; i < 128 * COLS / 4; i += 256) {
        int r = i / (COLS / 4), n4 = i % (COLS / 4);
        float4 v = __ldg((const float4*)W + i);
        __half2 h0 = __floats2half2_rn(v.x, v.y);
        __half2 h1 = __floats2half2_rn(v.z, v.w);
        uint2 u;
        u.x = *(unsigned*)&h0;
        u.y = *(unsigned*)&h1;
        *(uint2*)(smW + r * WROW + n4 * 8) = u;
    }
    __syncthreads();

    const int warp = tid >> 5;
    const int lane = tid & 31;
    const int warprow = warp * 16;
    const int lr = lane & 7;
    const int sel = lane >> 3;
    const int selLo = sel & 1;
    const int selHi = sel >> 1;

    float c[NT][4];
#pragma unroll
    for (int n = 0; n < NT; n++)
#pragma unroll
        for (int q = 0; q < 4; q++) c[n][q] = 0.f;

#pragma unroll
    for (int ks = 0; ks < 8; ks++) {
        unsigned a0, a1, a2, a3;
        unsigned aaddr = sA + (warprow + lr + selLo * 8) * AROW + ks * 32 + selHi * 16;
        asm volatile("ldmatrix.sync.aligned.m8n8.x4.shared.b16 {%0,%1,%2,%3}, [%4];"
                     : "=r"(a0), "=r"(a1), "=r"(a2), "=r"(a3) : "r"(aaddr));
#pragma unroll
        for (int p = 0; p < NT / 2; p++) {
            unsigned b0, b1, b2, b3;
            unsigned baddr = sW + (ks * 16 + lr + selLo * 8) * WROW + p * 32 + selHi * 16;
            asm volatile("ldmatrix.sync.aligned.m8n8.x4.trans.shared.b16 {%0,%1,%2,%3}, [%4];"
                         : "=r"(b0), "=r"(b1), "=r"(b2), "=r"(b3) : "r"(baddr));
            asm volatile("mma.sync.aligned.m16n8k16.row.col.f32.f16.f16.f32 "
                         "{%0,%1,%2,%3}, {%4,%5,%6,%7}, {%8,%9}, {%0,%1,%2,%3};"
                         : "+f"(c[2 * p][0]), "+f"(c[2 * p][1]), "+f"(c[2 * p][2]), "+f"(c[2 * p][3])
                         : "r"(a0), "r"(a1), "r"(a2), "r"(a3), "r"(b0), "r"(b1));
            asm volatile("mma.sync.aligned.m16n8k16.row.col.f32.f16.f16.f32 "
                         "{%0,%1,%2,%3}, {%4,%5,%6,%7}, {%8,%9}, {%0,%1,%2,%3};"
                         : "+f"(c[2 * p + 1][0]), "+f"(c[2 * p + 1][1]), "+f"(c[2 * p + 1][2]), "+f"(c[2 * p + 1][3])
                         : "r"(a0), "r"(a1), "r"(a2), "r"(a3), "r"(b2), "r"(b3));
        }
    }

    const int gq = lane >> 2;
    const int tig = lane & 3;
    int row0 = base + warprow + gq;
    int row1 = row0 + 8;
    float dv0 = (row0 < N) ? d_dinv[row0] : 0.f;
    float dv1 = (row1 < N) ? d_dinv[row1] : 0.f;
#pragma unroll
    for (int n = 0; n < NT; n++) {
        int col = n * 8 + 2 * tig;
        if (row0 < N) {
            __half2 h = __floats2half2_rn(c[n][0] * dv0, c[n][1] * dv0);
            *(__half2*)(g + (size_t)row0 * COLS + col) = h;
        }
        if (row1 < N) {
            __half2 h = __floats2half2_rn(c[n][2] * dv1, c[n][3] * dv1);
            *(__half2*)(g + (size_t)row1 * COLS + col) = h;
        }
    }
}

// ================= CSR aggregate (LDG.128 cooperative gather) ====================
__device__ __forceinline__ void acc_u4(float* a, uint4 v) {
    float2 f;
    f = __half22float2(*(__half2*)&v.x); a[0] += f.x; a[1] += f.y;
    f = __half22float2(*(__half2*)&v.y); a[2] += f.x; a[3] += f.y;
    f = __half22float2(*(__half2*)&v.z); a[4] += f.x; a[5] += f.y;
    f = __half22float2(*(__half2*)&v.w); a[6] += f.x; a[7] += f.y;
}

// 128 cols: half-warp (16 lanes x uint4 = 256B) per row, 2 neighbors per LDG.128.
// Lane in half h accumulates cols sl*8..sl*8+7 over edge subset h; shfl_xor(16)
// combines; lanes 0-15 write.
__global__ void k_agg128(const __half* __restrict__ g, const float* __restrict__ bias,
                         __half* __restrict__ out, int N)
{
    int node = (blockIdx.x * blockDim.x + threadIdx.x) >> 5;
    int lane = threadIdx.x & 31;
    if (node >= N) return;
    const uint4* gp = (const uint4*)g;
    const int hf = lane >> 4;
    const int sl = lane & 15;

    float a[8] = {0, 0, 0, 0, 0, 0, 0, 0};
    if (hf == 0)                                         // self-loop once
        acc_u4(a, __ldg(&gp[(size_t)node * 16 + sl]));

    int s = d_off[node], e = d_off[node + 1];
    int j = s;
    int c0, c1, c2, c3, c4, c5, c6, c7;
    bool have = (j + 8 <= e);
    if (have) {
        c0 = __ldg(d_csr + j);     c1 = __ldg(d_csr + j + 1);
        c2 = __ldg(d_csr + j + 2); c3 = __ldg(d_csr + j + 3);
        c4 = __ldg(d_csr + j + 4); c5 = __ldg(d_csr + j + 5);
        c6 = __ldg(d_csr + j + 6); c7 = __ldg(d_csr + j + 7);
    }
    while (have) {
        bool nxt = (j + 16 <= e);
        int m0, m1, m2, m3, m4, m5, m6, m7;
        if (nxt) {
            m0 = __ldg(d_csr + j + 8);  m1 = __ldg(d_csr + j + 9);
            m2 = __ldg(d_csr + j + 10); m3 = __ldg(d_csr + j + 11);
            m4 = __ldg(d_csr + j + 12); m5 = __ldg(d_csr + j + 13);
            m6 = __ldg(d_csr + j + 14); m7 = __ldg(d_csr + j + 15);
        }
        int e0 = hf ? c1 : c0;
        int e1 = hf ? c3 : c2;
        int e2 = hf ? c5 : c4;
        int e3 = hf ? c7 : c6;
        uint4 v0 = __ldg(&gp[(size_t)e0 * 16 + sl]);
        uint4 v1 = __ldg(&gp[(size_t)e1 * 16 + sl]);
        uint4 v2 = __ldg(&gp[(size_t)e2 * 16 + sl]);
        uint4 v3 = __ldg(&gp[(size_t)e3 * 16 + sl]);
        acc_u4(a, v0); acc_u4(a, v1); acc_u4(a, v2); acc_u4(a, v3);
        c0 = m0; c1 = m1; c2 = m2; c3 = m3;
        c4 = m4; c5 = m5; c6 = m6; c7 = m7;
        j += 8;
        have = nxt;
    }
    for (; j + 2 <= e; j += 2) {
        int n0 = __ldg(d_csr + j), n1 = __ldg(d_csr + j + 1);
        int nb = hf ? n1 : n0;
        acc_u4(a, __ldg(&gp[(size_t)nb * 16 + sl]));
    }
    if (j < e && hf == 0) {
        int nb = __ldg(d_csr + j);
        acc_u4(a, __ldg(&gp[(size_t)nb * 16 + sl]));
    }
#pragma unroll
    for (int i = 0; i < 8; i++)
        a[i] += __shfl_xor_sync(0xFFFFFFFFu, a[i], 16);

    if (hf == 0) {
        float dv = d_dinv[node];
        float4 b0 = __ldg((const float4*)bias + sl * 2);
        float4 b1 = __ldg((const float4*)bias + sl * 2 + 1);
        __half2 h[4];
        h[0] = __floats2half2_rn(fmaxf(fmaf(a[0], dv, b0.x), 0.f),
                                 fmaxf(fmaf(a[1], dv, b0.y), 0.f));
        h[1] = __floats2half2_rn(fmaxf(fmaf(a[2], dv, b0.z), 0.f),
                                 fmaxf(fmaf(a[3], dv, b0.w), 0.f));
        h[2] = __floats2half2_rn(fmaxf(fmaf(a[4], dv, b1.x), 0.f),
                                 fmaxf(fmaf(a[5], dv, b1.y), 0.f));
        h[3] = __floats2half2_rn(fmaxf(fmaf(a[6], dv, b1.z), 0.f),
                                 fmaxf(fmaf(a[7], dv, b1.w), 0.f));
        ((uint4*)out)[(size_t)node * 16 + sl] = *(uint4*)h;
    }
}

// 64 cols: quarter-warp (8 lanes x uint4 = 128B) per row, 4 neighbors per LDG.128.
// Combine via shfl_xor(8) + shfl_xor(16); fused min-pool (bias deferred).
__global__ void k_agg64min(const __half* __restrict__ g, int N)
{
    __shared__ unsigned sMin[64];
    int tid = threadIdx.x;
    if (tid < 64) sMin[tid] = 0xFFFFFFFFu;
    __syncthreads();

    int node = (blockIdx.x * blockDim.x + tid) >> 5;
    int lane = tid & 31;
    if (node < N) {
        const uint4* gp = (const uint4*)g;
        const int q = lane >> 3;
        const int sl = lane & 7;

        float a[8] = {0, 0, 0, 0, 0, 0, 0, 0};
        if (q == 0)
            acc_u4(a, __ldg(&gp[(size_t)node * 8 + sl]));

        int s = d_off[node], e = d_off[node + 1];
        int j = s;
        int c0, c1, c2, c3, c4, c5, c6, c7;
        bool have = (j + 8 <= e);
        if (have) {
            c0 = __ldg(d_csr + j);     c1 = __ldg(d_csr + j + 1);
            c2 = __ldg(d_csr + j + 2); c3 = __ldg(d_csr + j + 3);
            c4 = __ldg(d_csr + j + 4); c5 = __ldg(d_csr + j + 5);
            c6 = __ldg(d_csr + j + 6); c7 = __ldg(d_csr + j + 7);
        }
        while (have) {
            bool nxt = (j + 16 <= e);
            int m0, m1, m2, m3, m4, m5, m6, m7;
            if (nxt) {
                m0 = __ldg(d_csr + j + 8);  m1 = __ldg(d_csr + j + 9);
                m2 = __ldg(d_csr + j + 10); m3 = __ldg(d_csr + j + 11);
                m4 = __ldg(d_csr + j + 12); m5 = __ldg(d_csr + j + 13);
                m6 = __ldg(d_csr + j + 14); m7 = __ldg(d_csr + j + 15);
            }
            int ea = (q == 0) ? c0 : (q == 1) ? c1 : (q == 2) ? c2 : c3;
            int eb = (q == 0) ? c4 : (q == 1) ? c5 : (q == 2) ? c6 : c7;
            uint4 va = __ldg(&gp[(size_t)ea * 8 + sl]);
            uint4 vb = __ldg(&gp[(size_t)eb * 8 + sl]);
            acc_u4(a, va); acc_u4(a, vb);
            c0 = m0; c1 = m1; c2 = m2; c3 = m3;
            c4 = m4; c5 = m5; c6 = m6; c7 = m7;
            j += 8;
            have = nxt;
        }
        for (; j + 4 <= e; j += 4) {
            int n0 = __ldg(d_csr + j),     n1 = __ldg(d_csr + j + 1);
            int n2 = __ldg(d_csr + j + 2), n3 = __ldg(d_csr + j + 3);
            int nb = (q == 0) ? n0 : (q == 1) ? n1 : (q == 2) ? n2 : n3;
            acc_u4(a, __ldg(&gp[(size_t)nb * 8 + sl]));
        }
        int rem = e - j;
        if (q < rem) {
            int nb = __ldg(d_csr + j + q);
            acc_u4(a, __ldg(&gp[(size_t)nb * 8 + sl]));
        }
#pragma unroll
        for (int i = 0; i < 8; i++) {
            a[i] += __shfl_xor_sync(0xFFFFFFFFu, a[i], 8);
            a[i] += __shfl_xor_sync(0xFFFFFFFFu, a[i], 16);
        }
        if (q == 0) {
            float dv = d_dinv[node];
#pragma unroll
            for (int i = 0; i < 8; i++)
                atomicMin(&sMin[sl * 8 + i], enc_f(a[i] * dv));
        }
    }
    __syncthreads();
    if (tid < 64) atomicMin(&d_gmin[tid], sMin[tid]);
}

__global__ void k_final(const float* __restrict__ b3, float* __restrict__ out) {
    int c = threadIdx.x;
    out[c] = dec_f(d_gmin[c]) + b3[c];
}

extern "C" void kernel_launch(void* const* d_in, const int* in_sizes, int n_in,
                              void* d_out, int out_size)
{
    const float* x  = (const float*)d_in[0];
    const int*   ei = (const int*)d_in[1];
    const float* W1 = (const float*)d_in[2];
    const float* b1 = (const float*)d_in[3];
    const float* W2 = (const float*)d_in[4];
    const float* b2 = (const float*)d_in[5];
    const float* W3 = (const float*)d_in[6];
    const float* b3 = (const float*)d_in[7];
    float* out = (float*)d_out;

    int N = in_sizes[0] / 128;
    int E = in_sizes[1] / 2;
    const int* src = ei;
    const int* dst = ei + E;

    __half *B1, *B2, *G;
    cudaGetSymbolAddress((void**)&B1, d_B1);
    cudaGetSymbolAddress((void**)&B2, d_B2);
    cudaGetSymbolAddress((void**)&G, d_G);

    const int smem128 = 128 * 272 + 128 * 272;
    const int smem64  = 128 * 272 + 128 * 144;
    cudaFuncSetAttribute(k_gemm_mma<128, true,  float>,  cudaFuncAttributeMaxDynamicSharedMemorySize, smem128);
    cudaFuncSetAttribute(k_gemm_mma<128, false, __half>, cudaFuncAttributeMaxDynamicSharedMemorySize, smem128);
    cudaFuncSetAttribute(k_gemm_mma<64,  false, __half>, cudaFuncAttributeMaxDynamicSharedMemorySize, smem64);

    // CSR: hist + scans (dinv ready after scan3; cnt/cur self-cleaned there)
    k_hist<<<(E + 255) / 256, 256>>>(dst, E);
    int nblk = (N + 1023) / 1024;
    k_scan1<<<nblk, 256>>>(N);
    k_scan2<<<1, 128>>>(nblk);
    k_scan3<<<(N + 255) / 256, 256>>>(N, E);

    int gb = (N + 127) / 128;
    const int fillBlocks = 512;

    // Layer 1: tensor GEMM (x @ W1 -> G) with CSR fill fused at low block ids
    k_gemm_mma<128, true, float><<<gb + fillBlocks, 256, smem128>>>(x, W1, G, N, src, dst, E, fillBlocks);
    k_agg128<<<(N * 32 + 255) / 256, 256>>>(G, b1, B2, N);

    // Layer 2
    k_gemm_mma<128, false, __half><<<gb, 256, smem128>>>(B2, W2, G, N, nullptr, nullptr, 0, 0);
    k_agg128<<<(N * 32 + 255) / 256, 256>>>(G, b2, B1, N);

    // Layer 3 (64 cols) + fused min-pool
    k_gemm_mma<64, false, __half><<<gb, 256, smem64>>>(B1, W3, G, N, nullptr, nullptr, 0, 0);
    k_agg64min<<<(N * 32 + 255) / 256, 256>>>(G, N);

    k_final<<<1, 64>>>(b3, out);
}